// round 5
// baseline (speedup 1.0000x reference)
#include <cuda_runtime.h>
#include <cstdint>

#define NN 50000
#define EE 400000
#define TT 3
#define KD 256
#define HH 8
#define HD 32
#define CAP 64   // max in-degree bucket (Poisson(8): max~26, huge margin)

// ---- scratch (device globals; no allocs allowed) ----
__device__ float g_h[TT * NN * KD];       // per-type transformed features
__device__ float g_sl[TT * NN * HH];
__device__ float g_sr[TT * NN * HH];
__device__ int   g_cnt[TT * NN];
__device__ int   g_adj[TT * NN * CAP];
__device__ float4 g_x4[NN * KD / 2];      // x split: {hi0,lo0,hi1,lo1} per float4
__device__ float4 g_W4[TT * KD * KD / 2]; // W split, same layout

static __device__ __forceinline__ uint32_t s2u(const void* p) {
    uint32_t a;
    asm("{ .reg .u64 t; cvta.to.shared.u64 t, %1; cvt.u32.u64 %0, t; }" : "=r"(a) : "l"(p));
    return a;
}
static __device__ __forceinline__ void cp16(uint32_t dst, const void* src, int sz) {
    asm volatile("cp.async.cg.shared.global [%0], [%1], 16, %2;"
                 :: "r"(dst), "l"(src), "r"(sz) : "memory");
}
static __device__ __forceinline__ float f2tf(float f) {
    uint32_t r;
    asm("cvt.rna.tf32.f32 %0, %1;" : "=r"(r) : "f"(f));
    return __uint_as_float(r);
}
static __device__ __forceinline__ void mma8(float* c, uint32_t a0, uint32_t a1, uint32_t a2,
                                            uint32_t a3, uint32_t b0, uint32_t b1) {
    asm volatile(
        "mma.sync.aligned.m16n8k8.row.col.f32.tf32.tf32.f32 "
        "{%0,%1,%2,%3},{%4,%5,%6,%7},{%8,%9},{%0,%1,%2,%3};"
        : "+f"(c[0]), "+f"(c[1]), "+f"(c[2]), "+f"(c[3])
        : "r"(a0), "r"(a1), "r"(a2), "r"(a3), "r"(b0), "r"(b1));
}

// ---------------- prep: zero counters ----------------
__global__ void zero_cnt_kernel() {
    int i = blockIdx.x * blockDim.x + threadIdx.x;
    if (i < TT * NN) g_cnt[i] = 0;
}

// ---------------- prep: bucketed CSR build ----------------
__global__ void build_kernel(const int* __restrict__ ei) {
    int i = blockIdx.x * blockDim.x + threadIdx.x;
    if (i >= TT * EE) return;
    int t = i / EE, e = i - t * EE;
    int s = ei[t * 2 * EE + e];
    int d = ei[t * 2 * EE + EE + e];
    int pos = atomicAdd(&g_cnt[t * NN + d], 1);
    if (pos < CAP) g_adj[(t * NN + d) * CAP + pos] = s;
}

// ---------------- prep: tf32 hi/lo split of x and W ----------------
__global__ void split_x_kernel(const float* __restrict__ x) {
    int i = blockIdx.x * blockDim.x + threadIdx.x;   // pair index
    if (i >= NN * KD / 2) return;
    float2 v = ((const float2*)x)[i];
    float h0 = f2tf(v.x), h1 = f2tf(v.y);
    g_x4[i] = make_float4(h0, f2tf(v.x - h0), h1, f2tf(v.y - h1));
}
__global__ void split_W_kernel(const float* __restrict__ W) {
    int i = blockIdx.x * blockDim.x + threadIdx.x;
    if (i >= TT * KD * KD / 2) return;
    float2 v = ((const float2*)W)[i];
    float h0 = f2tf(v.x), h1 = f2tf(v.y);
    g_W4[i] = make_float4(h0, f2tf(v.x - h0), h1, f2tf(v.y - h1));
}

// ---------------- 3xTF32 mma.sync GEMM (pre-split operands) + score epilogue ----------------
// CTA 128x128xK256, BK=16, 8 warps 2x4, warp tile 64x32. Operands stored as (hi,lo)
// float2 in SMEM; fragment loads are single LDS.64, zero conversion math in-loop.
#define AS2 20    // A smem stride in float2 units (row offset = 8 banks: conflict-free)
#define BS2 132   // B smem stride in float2 units (row offset = 8 banks: conflict-free)
#define A_BUF_F2 (128 * AS2)
#define B_BUF_F2 (16 * BS2)
#define SM_TOTAL ((2 * A_BUF_F2 + 2 * B_BUF_F2) * 8)

__global__ void __launch_bounds__(256) gemm_scores_kernel(const float* __restrict__ a_l,
                                                          const float* __restrict__ a_r) {
    extern __shared__ float2 sm[];
    float2* As[2] = {sm, sm + A_BUF_F2};
    float2* Bs[2] = {sm + 2 * A_BUF_F2, sm + 2 * A_BUF_F2 + B_BUF_F2};

    const int tid = threadIdx.x;
    const int wid = tid >> 5, lane = tid & 31;
    const int g = lane >> 2, tg = lane & 3;
    const int wr = wid >> 2, wc = wid & 3;
    const int t = blockIdx.z;
    const int m0 = blockIdx.x * 128, n0 = blockIdx.y * 128;

    float acc[4][4][4];
#pragma unroll
    for (int i = 0; i < 4; i++)
#pragma unroll
        for (int j = 0; j < 4; j++)
#pragma unroll
            for (int q = 0; q < 4; q++) acc[i][j][q] = 0.f;

    auto loadTile = [&](int kt, int buf) {
        const int k0 = kt * 16;   // in original-element units
        uint32_t sa = s2u(As[buf]);
        uint32_t sb = s2u(Bs[buf]);
        // A: 128 rows x 16 elem-pairs = 1024 16B-chunks? rows x 8 chunks (2 elems each)
#pragma unroll
        for (int j = 0; j < 4; j++) {
            int c = tid + j * 256;          // 0..1023
            int r = c >> 3, cp = (c & 7) * 2;
            int gr = m0 + r;
            cp16(sa + (uint32_t)(r * AS2 + cp) * 8,
                 (const char*)g_x4 + ((size_t)gr * KD + k0 + cp) * 8,
                 gr < NN ? 16 : 0);
        }
        // B: 16 rows x 128 elems = 1024 chunks
#pragma unroll
        for (int j = 0; j < 4; j++) {
            int c = tid + j * 256;
            int r = c >> 6, cp = (c & 63) * 2;
            cp16(sb + (uint32_t)(r * BS2 + cp) * 8,
                 (const char*)g_W4 + (((size_t)t << 16) + (size_t)(k0 + r) * KD + n0 + cp) * 8,
                 16);
        }
        asm volatile("cp.async.commit_group;" ::: "memory");
    };

    loadTile(0, 0);

    for (int kt = 0; kt < 16; kt++) {
        const int buf = kt & 1;
        if (kt < 15) loadTile(kt + 1, buf ^ 1);
        if (kt < 15) asm volatile("cp.async.wait_group 1;" ::: "memory");
        else         asm volatile("cp.async.wait_group 0;" ::: "memory");
        __syncthreads();

        const float2* Ab = As[buf];
        const float2* Bb = Bs[buf];
#pragma unroll
        for (int kk = 0; kk < 16; kk += 8) {
            uint32_t ahi[4][4], alo[4][4], bhi[4][2], blo[4][2];
#pragma unroll
            for (int mf = 0; mf < 4; mf++) {
                int mr = wr * 64 + mf * 16;
                float2 p0 = Ab[(mr + g) * AS2 + kk + tg];
                float2 p1 = Ab[(mr + g + 8) * AS2 + kk + tg];
                float2 p2 = Ab[(mr + g) * AS2 + kk + tg + 4];
                float2 p3 = Ab[(mr + g + 8) * AS2 + kk + tg + 4];
                ahi[mf][0] = __float_as_uint(p0.x); alo[mf][0] = __float_as_uint(p0.y);
                ahi[mf][1] = __float_as_uint(p1.x); alo[mf][1] = __float_as_uint(p1.y);
                ahi[mf][2] = __float_as_uint(p2.x); alo[mf][2] = __float_as_uint(p2.y);
                ahi[mf][3] = __float_as_uint(p3.x); alo[mf][3] = __float_as_uint(p3.y);
            }
#pragma unroll
            for (int nf = 0; nf < 4; nf++) {
                int nc = wc * 32 + nf * 8;
                float2 q0 = Bb[(kk + tg) * BS2 + nc + g];
                float2 q1 = Bb[(kk + tg + 4) * BS2 + nc + g];
                bhi[nf][0] = __float_as_uint(q0.x); blo[nf][0] = __float_as_uint(q0.y);
                bhi[nf][1] = __float_as_uint(q1.x); blo[nf][1] = __float_as_uint(q1.y);
            }
#pragma unroll
            for (int mf = 0; mf < 4; mf++)
#pragma unroll
                for (int nf = 0; nf < 4; nf++) {
                    mma8(acc[mf][nf], ahi[mf][0], ahi[mf][1], ahi[mf][2], ahi[mf][3],
                         bhi[nf][0], bhi[nf][1]);
                    mma8(acc[mf][nf], ahi[mf][0], ahi[mf][1], ahi[mf][2], ahi[mf][3],
                         blo[nf][0], blo[nf][1]);
                    mma8(acc[mf][nf], alo[mf][0], alo[mf][1], alo[mf][2], alo[mf][3],
                         bhi[nf][0], bhi[nf][1]);
                }
        }
        __syncthreads();
    }

    // ---- epilogue: store h, compute per-head attention scores ----
    const int head = blockIdx.y * 4 + wc;
    float wl[4][2], wrt[4][2];
#pragma unroll
    for (int nf = 0; nf < 4; nf++) {
        int lc = nf * 8 + tg * 2;
        wl[nf][0]  = __ldg(a_l + ((size_t)t * HH + head) * HD + lc);
        wl[nf][1]  = __ldg(a_l + ((size_t)t * HH + head) * HD + lc + 1);
        wrt[nf][0] = __ldg(a_r + ((size_t)t * HH + head) * HD + lc);
        wrt[nf][1] = __ldg(a_r + ((size_t)t * HH + head) * HD + lc + 1);
    }
#pragma unroll
    for (int mf = 0; mf < 4; mf++) {
        int r0 = m0 + wr * 64 + mf * 16 + g;
        int r1 = r0 + 8;
        float dl0 = 0.f, dr0 = 0.f, dl1 = 0.f, dr1 = 0.f;
#pragma unroll
        for (int nf = 0; nf < 4; nf++) {
            int col = n0 + wc * 32 + nf * 8 + tg * 2;
            float c0 = acc[mf][nf][0], c1 = acc[mf][nf][1];
            float c2 = acc[mf][nf][2], c3 = acc[mf][nf][3];
            dl0 += c0 * wl[nf][0] + c1 * wl[nf][1];
            dr0 += c0 * wrt[nf][0] + c1 * wrt[nf][1];
            dl1 += c2 * wl[nf][0] + c3 * wl[nf][1];
            dr1 += c2 * wrt[nf][0] + c3 * wrt[nf][1];
            if (r0 < NN) *(float2*)&g_h[((size_t)t * NN + r0) * KD + col] = make_float2(c0, c1);
            if (r1 < NN) *(float2*)&g_h[((size_t)t * NN + r1) * KD + col] = make_float2(c2, c3);
        }
#pragma unroll
        for (int o = 1; o <= 2; o <<= 1) {
            dl0 += __shfl_xor_sync(0xffffffffu, dl0, o);
            dr0 += __shfl_xor_sync(0xffffffffu, dr0, o);
            dl1 += __shfl_xor_sync(0xffffffffu, dl1, o);
            dr1 += __shfl_xor_sync(0xffffffffu, dr1, o);
        }
        if (tg == 0) {
            if (r0 < NN) {
                g_sl[((size_t)t * NN + r0) * HH + head] = dl0;
                g_sr[((size_t)t * NN + r0) * HH + head] = dr0;
            }
            if (r1 < NN) {
                g_sl[((size_t)t * NN + r1) * HH + head] = dl1;
                g_sr[((size_t)t * NN + r1) * HH + head] = dr1;
            }
        }
    }
}

// ---------------- fused gather-aggregate + semantic attention ----------------
// One warp per dst node; 4-wide edge unroll for MLP; all state in registers.
__global__ void __launch_bounds__(256) agg_sem_kernel(const float* __restrict__ att_w,
                                                      const float* __restrict__ att_b,
                                                      float* __restrict__ out) {
    int n = (blockIdx.x * blockDim.x + threadIdx.x) >> 5;
    int lane = threadIdx.x & 31;
    if (n >= NN) return;
    int head = lane >> 2;

    float4 o0[TT], o1[TT];

#pragma unroll
    for (int t = 0; t < TT; t++) {
        float srv = g_sr[((size_t)t * NN + n) * HH + head];
        int cnt = g_cnt[t * NN + n];
        cnt = cnt < CAP ? cnt : CAP;
        const int* adj = g_adj + ((size_t)t * NN + n) * CAP;
        float4 a0 = make_float4(0.f, 0.f, 0.f, 0.f);
        float4 a1 = make_float4(0.f, 0.f, 0.f, 0.f);
        float den = 0.f;
        int e = 0;
        for (; e + 4 <= cnt; e += 4) {
            int4 s4 = *(const int4*)(adj + e);   // CAP=64-aligned base, e%4==0 -> 16B ok
            float sc0 = __ldg(g_sl + ((size_t)t * NN + s4.x) * HH + head) + srv;
            float sc1 = __ldg(g_sl + ((size_t)t * NN + s4.y) * HH + head) + srv;
            float sc2 = __ldg(g_sl + ((size_t)t * NN + s4.z) * HH + head) + srv;
            float sc3 = __ldg(g_sl + ((size_t)t * NN + s4.w) * HH + head) + srv;
            const float4* p0 = (const float4*)(g_h + ((size_t)t * NN + s4.x) * KD + lane * 8);
            const float4* p1 = (const float4*)(g_h + ((size_t)t * NN + s4.y) * KD + lane * 8);
            const float4* p2 = (const float4*)(g_h + ((size_t)t * NN + s4.z) * KD + lane * 8);
            const float4* p3 = (const float4*)(g_h + ((size_t)t * NN + s4.w) * KD + lane * 8);
            float4 u00 = p0[0], u01 = p0[1];
            float4 u10 = p1[0], u11 = p1[1];
            float4 u20 = p2[0], u21 = p2[1];
            float4 u30 = p3[0], u31 = p3[1];
            sc0 = sc0 > 0.f ? sc0 : 0.2f * sc0;
            sc1 = sc1 > 0.f ? sc1 : 0.2f * sc1;
            sc2 = sc2 > 0.f ? sc2 : 0.2f * sc2;
            sc3 = sc3 > 0.f ? sc3 : 0.2f * sc3;
            float x0 = __expf(sc0), x1 = __expf(sc1), x2 = __expf(sc2), x3 = __expf(sc3);
            den += (x0 + x1) + (x2 + x3);
            a0.x += x0 * u00.x + x1 * u10.x + x2 * u20.x + x3 * u30.x;
            a0.y += x0 * u00.y + x1 * u10.y + x2 * u20.y + x3 * u30.y;
            a0.z += x0 * u00.z + x1 * u10.z + x2 * u20.z + x3 * u30.z;
            a0.w += x0 * u00.w + x1 * u10.w + x2 * u20.w + x3 * u30.w;
            a1.x += x0 * u01.x + x1 * u11.x + x2 * u21.x + x3 * u31.x;
            a1.y += x0 * u01.y + x1 * u11.y + x2 * u21.y + x3 * u31.y;
            a1.z += x0 * u01.z + x1 * u11.z + x2 * u21.z + x3 * u31.z;
            a1.w += x0 * u01.w + x1 * u11.w + x2 * u21.w + x3 * u31.w;
        }
        for (; e < cnt; e++) {
            int s0 = __ldg(adj + e);
            float sc0 = __ldg(g_sl + ((size_t)t * NN + s0) * HH + head) + srv;
            const float4* p0 = (const float4*)(g_h + ((size_t)t * NN + s0) * KD + lane * 8);
            float4 u0 = p0[0], u1 = p0[1];
            sc0 = sc0 > 0.f ? sc0 : 0.2f * sc0;
            float x0 = __expf(sc0);
            den += x0;
            a0.x += x0 * u0.x; a0.y += x0 * u0.y; a0.z += x0 * u0.z; a0.w += x0 * u0.w;
            a1.x += x0 * u1.x; a1.y += x0 * u1.y; a1.z += x0 * u1.z; a1.w += x0 * u1.w;
        }
        float inv = den > 0.f ? __frcp_rn(den) : 1.f;
        o0[t] = make_float4(a0.x * inv, a0.y * inv, a0.z * inv, a0.w * inv);
        o1[t] = make_float4(a1.x * inv, a1.y * inv, a1.z * inv, a1.w * inv);
    }

    // semantic attention
    float4 w0 = ((const float4*)att_w)[lane * 2];
    float4 w1 = ((const float4*)att_w)[lane * 2 + 1];
    float b = att_b[0];
    float4 acc0 = make_float4(0.f, 0.f, 0.f, 0.f);
    float4 acc1 = make_float4(0.f, 0.f, 0.f, 0.f);
#pragma unroll
    for (int t = 0; t < TT; t++) {
        float p = o0[t].x * w0.x + o0[t].y * w0.y + o0[t].z * w0.z + o0[t].w * w0.w
                + o1[t].x * w1.x + o1[t].y * w1.y + o1[t].z * w1.z + o1[t].w * w1.w;
#pragma unroll
        for (int o = 16; o; o >>= 1) p += __shfl_xor_sync(0xffffffffu, p, o);
        float att = p + b;
        acc0.x += att * o0[t].x; acc0.y += att * o0[t].y;
        acc0.z += att * o0[t].z; acc0.w += att * o0[t].w;
        acc1.x += att * o1[t].x; acc1.y += att * o1[t].y;
        acc1.z += att * o1[t].z; acc1.w += att * o1[t].w;
    }
    float4* dp = (float4*)(out + (size_t)n * KD + lane * 8);
    dp[0] = acc0;
    dp[1] = acc1;
}

extern "C" void kernel_launch(void* const* d_in, const int* in_sizes, int n_in,
                              void* d_out, int out_size) {
    const float* x     = (const float*)d_in[0];
    const int*   ei    = (const int*)d_in[1];
    const float* W     = (const float*)d_in[2];
    const float* a_l   = (const float*)d_in[3];
    const float* a_r   = (const float*)d_in[4];
    const float* att_w = (const float*)d_in[5];
    const float* att_b = (const float*)d_in[6];
    float* out = (float*)d_out;

    static int smem_set = 0;
    if (!smem_set) {
        cudaFuncSetAttribute(gemm_scores_kernel,
                             cudaFuncAttributeMaxDynamicSharedMemorySize, SM_TOTAL);
        smem_set = 1;
    }

    zero_cnt_kernel<<<(TT * NN + 255) / 256, 256>>>();
    build_kernel<<<(TT * EE + 255) / 256, 256>>>(ei);
    split_x_kernel<<<(NN * KD / 2 + 255) / 256, 256>>>(x);
    split_W_kernel<<<(TT * KD * KD / 2 + 255) / 256, 256>>>(W);

    dim3 ggrid((NN + 127) / 128, 2, TT);
    gemm_scores_kernel<<<ggrid, 256, SM_TOTAL>>>(a_l, a_r);

    agg_sem_kernel<<<(NN * 32 + 255) / 256, 256>>>(att_w, att_b, out);
}

// round 6
// speedup vs baseline: 1.3572x; 1.3572x over previous
#include <cuda_runtime.h>
#include <cstdint>

#define NN 50000
#define EE 400000
#define TT 3
#define KD 256
#define HH 8
#define HD 32
#define CAP 64   // max in-degree bucket (Poisson(8): max~26, huge margin)

// ---- scratch (device globals; no allocs allowed) ----
__device__ float  g_h[TT * NN * KD];      // per-type transformed features
__device__ float  g_sl[TT * NN * HH];
__device__ float  g_sr[TT * NN * HH];
__device__ int    g_cnt[TT * NN];
__device__ int    g_adj[TT * NN * CAP];
__device__ float2 g_W2[TT * KD * KD];     // W split: {hi, lo} per element (1.5 MB, L2-resident)

static __device__ __forceinline__ uint32_t s2u(const void* p) {
    uint32_t a;
    asm("{ .reg .u64 t; cvta.to.shared.u64 t, %1; cvt.u32.u64 %0, t; }" : "=r"(a) : "l"(p));
    return a;
}
static __device__ __forceinline__ void cp16(uint32_t dst, const void* src, int sz) {
    asm volatile("cp.async.cg.shared.global [%0], [%1], 16, %2;"
                 :: "r"(dst), "l"(src), "r"(sz) : "memory");
}
static __device__ __forceinline__ float f2tf(float f) {
    uint32_t r;
    asm("cvt.rna.tf32.f32 %0, %1;" : "=r"(r) : "f"(f));
    return __uint_as_float(r);
}
static __device__ __forceinline__ void mma8(float* c, uint32_t a0, uint32_t a1, uint32_t a2,
                                            uint32_t a3, uint32_t b0, uint32_t b1) {
    asm volatile(
        "mma.sync.aligned.m16n8k8.row.col.f32.tf32.tf32.f32 "
        "{%0,%1,%2,%3},{%4,%5,%6,%7},{%8,%9},{%0,%1,%2,%3};"
        : "+f"(c[0]), "+f"(c[1]), "+f"(c[2]), "+f"(c[3])
        : "r"(a0), "r"(a1), "r"(a2), "r"(a3), "r"(b0), "r"(b1));
}

// ---------------- prep: zero counters ----------------
__global__ void zero_cnt_kernel() {
    int i = blockIdx.x * blockDim.x + threadIdx.x;
    if (i < TT * NN) g_cnt[i] = 0;
}

// ---------------- prep: bucketed CSR build ----------------
__global__ void build_kernel(const int* __restrict__ ei) {
    int i = blockIdx.x * blockDim.x + threadIdx.x;
    if (i >= TT * EE) return;
    int t = i / EE, e = i - t * EE;
    int s = ei[t * 2 * EE + e];
    int d = ei[t * 2 * EE + EE + e];
    int pos = atomicAdd(&g_cnt[t * NN + d], 1);
    if (pos < CAP) g_adj[(t * NN + d) * CAP + pos] = s;
}

// ---------------- prep: tf32 hi/lo split of W only (small, L2-resident) ----------------
__global__ void split_W_kernel(const float* __restrict__ W) {
    int i = blockIdx.x * blockDim.x + threadIdx.x;
    if (i >= TT * KD * KD) return;
    float v = W[i];
    float h = f2tf(v);
    g_W2[i] = make_float2(h, f2tf(v - h));
}

// ---------------- 2xTF32 mma.sync GEMM: acc = ahi*(bhi+blo), score epilogue ----------------
// CTA 128x128xK256, BK=16, 8 warps 2x4, warp tile 64x32.
// A: plain float SMEM (stride 20, conflict-free), hi-cvt in loop (error term dropped).
// B: pre-split (hi,lo) float2 SMEM (stride 132, conflict-free LDS.64).
#define AS_STR 20
#define BS2 132
#define A_BUF_F  (128 * AS_STR)             // floats
#define B_BUF_F2 (16 * BS2)                 // float2
#define SM_TOTAL (2 * A_BUF_F * 4 + 2 * B_BUF_F2 * 8)   // 20480 + 33792 = 54272 B

__global__ void __launch_bounds__(256) gemm_scores_kernel(const float* __restrict__ x,
                                                          const float* __restrict__ a_l,
                                                          const float* __restrict__ a_r) {
    extern __shared__ char smraw[];
    float*  Asb[2] = {(float*)smraw, (float*)smraw + A_BUF_F};
    float2* Bsb[2] = {(float2*)(smraw + 2 * A_BUF_F * 4),
                      (float2*)(smraw + 2 * A_BUF_F * 4) + B_BUF_F2};

    const int tid = threadIdx.x;
    const int wid = tid >> 5, lane = tid & 31;
    const int g = lane >> 2, tg = lane & 3;
    const int wr = wid >> 2, wc = wid & 3;
    const int t = blockIdx.z;
    const int m0 = blockIdx.x * 128, n0 = blockIdx.y * 128;

    float acc[4][4][4];
#pragma unroll
    for (int i = 0; i < 4; i++)
#pragma unroll
        for (int j = 0; j < 4; j++)
#pragma unroll
            for (int q = 0; q < 4; q++) acc[i][j][q] = 0.f;

    const int arow = tid >> 2, aq = (tid & 3) * 4;

    auto loadTile = [&](int kt, int buf) {
        const int k0 = kt * 16;
        uint32_t sa = s2u(Asb[buf]);
        uint32_t sb = s2u(Bsb[buf]);
        // A: 128 rows x 16 floats
#pragma unroll
        for (int j = 0; j < 2; j++) {
            int r = arow + j * 64;
            int gr = m0 + r;
            cp16(sa + (uint32_t)(r * AS_STR + aq) * 4,
                 x + (size_t)gr * KD + k0 + aq, gr < NN ? 16 : 0);
        }
        // B: 16 rows x 128 float2 = 1024 16B-chunks (2 float2 each)
#pragma unroll
        for (int j = 0; j < 4; j++) {
            int c = tid + j * 256;
            int r = c >> 6, cp = (c & 63) * 2;
            cp16(sb + (uint32_t)(r * BS2 + cp) * 8,
                 (const char*)g_W2 + (((size_t)t << 16) + (size_t)(k0 + r) * KD + n0 + cp) * 8,
                 16);
        }
        asm volatile("cp.async.commit_group;" ::: "memory");
    };

    loadTile(0, 0);

    for (int kt = 0; kt < 16; kt++) {
        const int buf = kt & 1;
        if (kt < 15) loadTile(kt + 1, buf ^ 1);
        if (kt < 15) asm volatile("cp.async.wait_group 1;" ::: "memory");
        else         asm volatile("cp.async.wait_group 0;" ::: "memory");
        __syncthreads();

        const float* Ab = Asb[buf];
        const float2* Bb = Bsb[buf];
#pragma unroll
        for (int kk = 0; kk < 16; kk += 8) {
            uint32_t ahi[4][4], bhi[4][2], blo[4][2];
#pragma unroll
            for (int mf = 0; mf < 4; mf++) {
                int mr = wr * 64 + mf * 16;
                ahi[mf][0] = __float_as_uint(f2tf(Ab[(mr + g) * AS_STR + kk + tg]));
                ahi[mf][1] = __float_as_uint(f2tf(Ab[(mr + g + 8) * AS_STR + kk + tg]));
                ahi[mf][2] = __float_as_uint(f2tf(Ab[(mr + g) * AS_STR + kk + tg + 4]));
                ahi[mf][3] = __float_as_uint(f2tf(Ab[(mr + g + 8) * AS_STR + kk + tg + 4]));
            }
#pragma unroll
            for (int nf = 0; nf < 4; nf++) {
                int nc = wc * 32 + nf * 8;
                float2 q0 = Bb[(kk + tg) * BS2 + nc + g];
                float2 q1 = Bb[(kk + tg + 4) * BS2 + nc + g];
                bhi[nf][0] = __float_as_uint(q0.x); blo[nf][0] = __float_as_uint(q0.y);
                bhi[nf][1] = __float_as_uint(q1.x); blo[nf][1] = __float_as_uint(q1.y);
            }
#pragma unroll
            for (int mf = 0; mf < 4; mf++)
#pragma unroll
                for (int nf = 0; nf < 4; nf++) {
                    mma8(acc[mf][nf], ahi[mf][0], ahi[mf][1], ahi[mf][2], ahi[mf][3],
                         bhi[nf][0], bhi[nf][1]);
                    mma8(acc[mf][nf], ahi[mf][0], ahi[mf][1], ahi[mf][2], ahi[mf][3],
                         blo[nf][0], blo[nf][1]);
                }
        }
        __syncthreads();
    }

    // ---- epilogue: store h, compute per-head attention scores ----
    const int head = blockIdx.y * 4 + wc;
    float wl[4][2], wrt[4][2];
#pragma unroll
    for (int nf = 0; nf < 4; nf++) {
        int lc = nf * 8 + tg * 2;
        wl[nf][0]  = __ldg(a_l + ((size_t)t * HH + head) * HD + lc);
        wl[nf][1]  = __ldg(a_l + ((size_t)t * HH + head) * HD + lc + 1);
        wrt[nf][0] = __ldg(a_r + ((size_t)t * HH + head) * HD + lc);
        wrt[nf][1] = __ldg(a_r + ((size_t)t * HH + head) * HD + lc + 1);
    }
#pragma unroll
    for (int mf = 0; mf < 4; mf++) {
        int r0 = m0 + wr * 64 + mf * 16 + g;
        int r1 = r0 + 8;
        float dl0 = 0.f, dr0 = 0.f, dl1 = 0.f, dr1 = 0.f;
#pragma unroll
        for (int nf = 0; nf < 4; nf++) {
            int col = n0 + wc * 32 + nf * 8 + tg * 2;
            float c0 = acc[mf][nf][0], c1 = acc[mf][nf][1];
            float c2 = acc[mf][nf][2], c3 = acc[mf][nf][3];
            dl0 += c0 * wl[nf][0] + c1 * wl[nf][1];
            dr0 += c0 * wrt[nf][0] + c1 * wrt[nf][1];
            dl1 += c2 * wl[nf][0] + c3 * wl[nf][1];
            dr1 += c2 * wrt[nf][0] + c3 * wrt[nf][1];
            if (r0 < NN) *(float2*)&g_h[((size_t)t * NN + r0) * KD + col] = make_float2(c0, c1);
            if (r1 < NN) *(float2*)&g_h[((size_t)t * NN + r1) * KD + col] = make_float2(c2, c3);
        }
#pragma unroll
        for (int o = 1; o <= 2; o <<= 1) {
            dl0 += __shfl_xor_sync(0xffffffffu, dl0, o);
            dr0 += __shfl_xor_sync(0xffffffffu, dr0, o);
            dl1 += __shfl_xor_sync(0xffffffffu, dl1, o);
            dr1 += __shfl_xor_sync(0xffffffffu, dr1, o);
        }
        if (tg == 0) {
            if (r0 < NN) {
                g_sl[((size_t)t * NN + r0) * HH + head] = dl0;
                g_sr[((size_t)t * NN + r0) * HH + head] = dr0;
            }
            if (r1 < NN) {
                g_sl[((size_t)t * NN + r1) * HH + head] = dl1;
                g_sr[((size_t)t * NN + r1) * HH + head] = dr1;
            }
        }
    }
}

// ---------------- fused gather-aggregate + semantic attention ----------------
// One warp per dst node; 4-wide edge unroll for MLP; all state in registers.
__global__ void __launch_bounds__(256) agg_sem_kernel(const float* __restrict__ att_w,
                                                      const float* __restrict__ att_b,
                                                      float* __restrict__ out) {
    int n = (blockIdx.x * blockDim.x + threadIdx.x) >> 5;
    int lane = threadIdx.x & 31;
    if (n >= NN) return;
    int head = lane >> 2;

    float4 o0[TT], o1[TT];

#pragma unroll
    for (int t = 0; t < TT; t++) {
        float srv = g_sr[((size_t)t * NN + n) * HH + head];
        int cnt = g_cnt[t * NN + n];
        cnt = cnt < CAP ? cnt : CAP;
        const int* adj = g_adj + ((size_t)t * NN + n) * CAP;
        float4 a0 = make_float4(0.f, 0.f, 0.f, 0.f);
        float4 a1 = make_float4(0.f, 0.f, 0.f, 0.f);
        float den = 0.f;
        int e = 0;
        for (; e + 4 <= cnt; e += 4) {
            int4 s4 = *(const int4*)(adj + e);
            float sc0 = __ldg(g_sl + ((size_t)t * NN + s4.x) * HH + head) + srv;
            float sc1 = __ldg(g_sl + ((size_t)t * NN + s4.y) * HH + head) + srv;
            float sc2 = __ldg(g_sl + ((size_t)t * NN + s4.z) * HH + head) + srv;
            float sc3 = __ldg(g_sl + ((size_t)t * NN + s4.w) * HH + head) + srv;
            const float4* p0 = (const float4*)(g_h + ((size_t)t * NN + s4.x) * KD + lane * 8);
            const float4* p1 = (const float4*)(g_h + ((size_t)t * NN + s4.y) * KD + lane * 8);
            const float4* p2 = (const float4*)(g_h + ((size_t)t * NN + s4.z) * KD + lane * 8);
            const float4* p3 = (const float4*)(g_h + ((size_t)t * NN + s4.w) * KD + lane * 8);
            float4 u00 = p0[0], u01 = p0[1];
            float4 u10 = p1[0], u11 = p1[1];
            float4 u20 = p2[0], u21 = p2[1];
            float4 u30 = p3[0], u31 = p3[1];
            sc0 = sc0 > 0.f ? sc0 : 0.2f * sc0;
            sc1 = sc1 > 0.f ? sc1 : 0.2f * sc1;
            sc2 = sc2 > 0.f ? sc2 : 0.2f * sc2;
            sc3 = sc3 > 0.f ? sc3 : 0.2f * sc3;
            float x0 = __expf(sc0), x1 = __expf(sc1), x2 = __expf(sc2), x3 = __expf(sc3);
            den += (x0 + x1) + (x2 + x3);
            a0.x += x0 * u00.x + x1 * u10.x + x2 * u20.x + x3 * u30.x;
            a0.y += x0 * u00.y + x1 * u10.y + x2 * u20.y + x3 * u30.y;
            a0.z += x0 * u00.z + x1 * u10.z + x2 * u20.z + x3 * u30.z;
            a0.w += x0 * u00.w + x1 * u10.w + x2 * u20.w + x3 * u30.w;
            a1.x += x0 * u01.x + x1 * u11.x + x2 * u21.x + x3 * u31.x;
            a1.y += x0 * u01.y + x1 * u11.y + x2 * u21.y + x3 * u31.y;
            a1.z += x0 * u01.z + x1 * u11.z + x2 * u21.z + x3 * u31.z;
            a1.w += x0 * u01.w + x1 * u11.w + x2 * u21.w + x3 * u31.w;
        }
        for (; e < cnt; e++) {
            int s0 = __ldg(adj + e);
            float sc0 = __ldg(g_sl + ((size_t)t * NN + s0) * HH + head) + srv;
            const float4* p0 = (const float4*)(g_h + ((size_t)t * NN + s0) * KD + lane * 8);
            float4 u0 = p0[0], u1 = p0[1];
            sc0 = sc0 > 0.f ? sc0 : 0.2f * sc0;
            float x0 = __expf(sc0);
            den += x0;
            a0.x += x0 * u0.x; a0.y += x0 * u0.y; a0.z += x0 * u0.z; a0.w += x0 * u0.w;
            a1.x += x0 * u1.x; a1.y += x0 * u1.y; a1.z += x0 * u1.z; a1.w += x0 * u1.w;
        }
        float inv = den > 0.f ? __frcp_rn(den) : 1.f;
        o0[t] = make_float4(a0.x * inv, a0.y * inv, a0.z * inv, a0.w * inv);
        o1[t] = make_float4(a1.x * inv, a1.y * inv, a1.z * inv, a1.w * inv);
    }

    // semantic attention
    float4 w0 = ((const float4*)att_w)[lane * 2];
    float4 w1 = ((const float4*)att_w)[lane * 2 + 1];
    float b = att_b[0];
    float4 acc0 = make_float4(0.f, 0.f, 0.f, 0.f);
    float4 acc1 = make_float4(0.f, 0.f, 0.f, 0.f);
#pragma unroll
    for (int t = 0; t < TT; t++) {
        float p = o0[t].x * w0.x + o0[t].y * w0.y + o0[t].z * w0.z + o0[t].w * w0.w
                + o1[t].x * w1.x + o1[t].y * w1.y + o1[t].z * w1.z + o1[t].w * w1.w;
#pragma unroll
        for (int o = 16; o; o >>= 1) p += __shfl_xor_sync(0xffffffffu, p, o);
        float att = p + b;
        acc0.x += att * o0[t].x; acc0.y += att * o0[t].y;
        acc0.z += att * o0[t].z; acc0.w += att * o0[t].w;
        acc1.x += att * o1[t].x; acc1.y += att * o1[t].y;
        acc1.z += att * o1[t].z; acc1.w += att * o1[t].w;
    }
    float4* dp = (float4*)(out + (size_t)n * KD + lane * 8);
    dp[0] = acc0;
    dp[1] = acc1;
}

extern "C" void kernel_launch(void* const* d_in, const int* in_sizes, int n_in,
                              void* d_out, int out_size) {
    const float* x     = (const float*)d_in[0];
    const int*   ei    = (const int*)d_in[1];
    const float* W     = (const float*)d_in[2];
    const float* a_l   = (const float*)d_in[3];
    const float* a_r   = (const float*)d_in[4];
    const float* att_w = (const float*)d_in[5];
    const float* att_b = (const float*)d_in[6];
    float* out = (float*)d_out;

    static int smem_set = 0;
    if (!smem_set) {
        cudaFuncSetAttribute(gemm_scores_kernel,
                             cudaFuncAttributeMaxDynamicSharedMemorySize, SM_TOTAL);
        smem_set = 1;
    }

    zero_cnt_kernel<<<(TT * NN + 255) / 256, 256>>>();
    build_kernel<<<(TT * EE + 255) / 256, 256>>>(ei);
    split_W_kernel<<<(TT * KD * KD + 255) / 256, 256>>>(W);

    dim3 ggrid((NN + 127) / 128, 2, TT);
    gemm_scores_kernel<<<ggrid, 256, SM_TOTAL>>>(x, a_l, a_r);

    agg_sem_kernel<<<(NN * 32 + 255) / 256, 256>>>(att_w, att_b, out);
}

// round 7
// speedup vs baseline: 1.5099x; 1.1125x over previous
#include <cuda_runtime.h>
#include <cstdint>

#define NN 50000
#define EE 400000
#define TT 3
#define KD 256
#define HH 8
#define HD 32
#define CAP 64   // max in-degree bucket (Poisson(8): max~26, huge margin)

// ---- scratch (device globals; no allocs allowed) ----
__device__ float  g_h[TT * NN * KD];      // per-type transformed features
__device__ float  g_sl[TT * NN * HH];
__device__ float  g_sr[TT * NN * HH];
__device__ int    g_cnt[TT * NN];
__device__ int    g_adj[TT * NN * CAP];
__device__ float2 g_W2[TT * KD * KD];     // W split: {hi, lo} per element (L2-resident)

static __device__ __forceinline__ uint32_t s2u(const void* p) {
    uint32_t a;
    asm("{ .reg .u64 t; cvta.to.shared.u64 t, %1; cvt.u32.u64 %0, t; }" : "=r"(a) : "l"(p));
    return a;
}
static __device__ __forceinline__ void cp16(uint32_t dst, const void* src, int sz) {
    asm volatile("cp.async.cg.shared.global [%0], [%1], 16, %2;"
                 :: "r"(dst), "l"(src), "r"(sz) : "memory");
}
static __device__ __forceinline__ float f2tf(float f) {
    uint32_t r;
    asm("cvt.rna.tf32.f32 %0, %1;" : "=r"(r) : "f"(f));
    return __uint_as_float(r);
}
static __device__ __forceinline__ void mma8(float* c, uint32_t a0, uint32_t a1, uint32_t a2,
                                            uint32_t a3, uint32_t b0, uint32_t b1) {
    asm volatile(
        "mma.sync.aligned.m16n8k8.row.col.f32.tf32.tf32.f32 "
        "{%0,%1,%2,%3},{%4,%5,%6,%7},{%8,%9},{%0,%1,%2,%3};"
        : "+f"(c[0]), "+f"(c[1]), "+f"(c[2]), "+f"(c[3])
        : "r"(a0), "r"(a1), "r"(a2), "r"(a3), "r"(b0), "r"(b1));
}

// ---------------- prep: zero counters ----------------
__global__ void zero_cnt_kernel() {
    int i = blockIdx.x * blockDim.x + threadIdx.x;
    if (i < TT * NN) g_cnt[i] = 0;
}

// ---------------- prep: bucketed CSR build ----------------
__global__ void build_kernel(const int* __restrict__ ei) {
    int i = blockIdx.x * blockDim.x + threadIdx.x;
    if (i >= TT * EE) return;
    int t = i / EE, e = i - t * EE;
    int s = ei[t * 2 * EE + e];
    int d = ei[t * 2 * EE + EE + e];
    int pos = atomicAdd(&g_cnt[t * NN + d], 1);
    if (pos < CAP) g_adj[(t * NN + d) * CAP + pos] = s;
}

// ---------------- prep: tf32 hi/lo split of W only (small, L2-resident) ----------------
__global__ void split_W_kernel(const float* __restrict__ W) {
    int i = blockIdx.x * blockDim.x + threadIdx.x;
    if (i >= TT * KD * KD) return;
    float v = W[i];
    float h = f2tf(v);
    g_W2[i] = make_float2(h, f2tf(v - h));
}

// ---------------- 2xTF32 mma.sync GEMM: acc = ahi*(bhi+blo), score epilogue ----------------
// CTA 128x128xK256, BK=16, 8 warps 2x4, warp tile 64x32, forced 2 CTAs/SM (<=128 regs).
// Inner loop restructured: B fragments loaded per-nf just before use (short live range).
#define AS_STR 20
#define BS2 132
#define A_BUF_F  (128 * AS_STR)
#define B_BUF_F2 (16 * BS2)
#define SM_TOTAL (2 * A_BUF_F * 4 + 2 * B_BUF_F2 * 8)   // 54272 B

__global__ void __launch_bounds__(256, 2) gemm_scores_kernel(const float* __restrict__ x,
                                                             const float* __restrict__ a_l,
                                                             const float* __restrict__ a_r) {
    extern __shared__ char smraw[];
    float*  Asb[2] = {(float*)smraw, (float*)smraw + A_BUF_F};
    float2* Bsb[2] = {(float2*)(smraw + 2 * A_BUF_F * 4),
                      (float2*)(smraw + 2 * A_BUF_F * 4) + B_BUF_F2};

    const int tid = threadIdx.x;
    const int wid = tid >> 5, lane = tid & 31;
    const int g = lane >> 2, tg = lane & 3;
    const int wr = wid >> 2, wc = wid & 3;
    const int t = blockIdx.z;
    const int m0 = blockIdx.x * 128, n0 = blockIdx.y * 128;

    float acc[4][4][4];
#pragma unroll
    for (int i = 0; i < 4; i++)
#pragma unroll
        for (int j = 0; j < 4; j++)
#pragma unroll
            for (int q = 0; q < 4; q++) acc[i][j][q] = 0.f;

    const int arow = tid >> 2, aq = (tid & 3) * 4;

    auto loadTile = [&](int kt, int buf) {
        const int k0 = kt * 16;
        uint32_t sa = s2u(Asb[buf]);
        uint32_t sb = s2u(Bsb[buf]);
#pragma unroll
        for (int j = 0; j < 2; j++) {
            int r = arow + j * 64;
            int gr = m0 + r;
            cp16(sa + (uint32_t)(r * AS_STR + aq) * 4,
                 x + (size_t)gr * KD + k0 + aq, gr < NN ? 16 : 0);
        }
#pragma unroll
        for (int j = 0; j < 4; j++) {
            int c = tid + j * 256;
            int r = c >> 6, cp = (c & 63) * 2;
            cp16(sb + (uint32_t)(r * BS2 + cp) * 8,
                 (const char*)g_W2 + (((size_t)t << 16) + (size_t)(k0 + r) * KD + n0 + cp) * 8,
                 16);
        }
        asm volatile("cp.async.commit_group;" ::: "memory");
    };

    loadTile(0, 0);

    for (int kt = 0; kt < 16; kt++) {
        const int buf = kt & 1;
        if (kt < 15) loadTile(kt + 1, buf ^ 1);
        if (kt < 15) asm volatile("cp.async.wait_group 1;" ::: "memory");
        else         asm volatile("cp.async.wait_group 0;" ::: "memory");
        __syncthreads();

        const float* Ab = Asb[buf];
        const float2* Bb = Bsb[buf];
#pragma unroll
        for (int kk = 0; kk < 16; kk += 8) {
            uint32_t ahi[4][4];
#pragma unroll
            for (int mf = 0; mf < 4; mf++) {
                int mr = wr * 64 + mf * 16;
                ahi[mf][0] = __float_as_uint(f2tf(Ab[(mr + g) * AS_STR + kk + tg]));
                ahi[mf][1] = __float_as_uint(f2tf(Ab[(mr + g + 8) * AS_STR + kk + tg]));
                ahi[mf][2] = __float_as_uint(f2tf(Ab[(mr + g) * AS_STR + kk + tg + 4]));
                ahi[mf][3] = __float_as_uint(f2tf(Ab[(mr + g + 8) * AS_STR + kk + tg + 4]));
            }
            // B fragments loaded per-nf and consumed immediately (short live range)
#pragma unroll
            for (int nf = 0; nf < 4; nf++) {
                int nc = wc * 32 + nf * 8;
                float2 q0 = Bb[(kk + tg) * BS2 + nc + g];
                float2 q1 = Bb[(kk + tg + 4) * BS2 + nc + g];
                uint32_t bh0 = __float_as_uint(q0.x), bl0 = __float_as_uint(q0.y);
                uint32_t bh1 = __float_as_uint(q1.x), bl1 = __float_as_uint(q1.y);
#pragma unroll
                for (int mf = 0; mf < 4; mf++) {
                    mma8(acc[mf][nf], ahi[mf][0], ahi[mf][1], ahi[mf][2], ahi[mf][3], bh0, bh1);
                    mma8(acc[mf][nf], ahi[mf][0], ahi[mf][1], ahi[mf][2], ahi[mf][3], bl0, bl1);
                }
            }
        }
        __syncthreads();
    }

    // ---- epilogue: store h, compute per-head attention scores ----
    const int head = blockIdx.y * 4 + wc;
    float wl[4][2], wrt[4][2];
#pragma unroll
    for (int nf = 0; nf < 4; nf++) {
        int lc = nf * 8 + tg * 2;
        wl[nf][0]  = __ldg(a_l + ((size_t)t * HH + head) * HD + lc);
        wl[nf][1]  = __ldg(a_l + ((size_t)t * HH + head) * HD + lc + 1);
        wrt[nf][0] = __ldg(a_r + ((size_t)t * HH + head) * HD + lc);
        wrt[nf][1] = __ldg(a_r + ((size_t)t * HH + head) * HD + lc + 1);
    }
#pragma unroll
    for (int mf = 0; mf < 4; mf++) {
        int r0 = m0 + wr * 64 + mf * 16 + g;
        int r1 = r0 + 8;
        float dl0 = 0.f, dr0 = 0.f, dl1 = 0.f, dr1 = 0.f;
#pragma unroll
        for (int nf = 0; nf < 4; nf++) {
            int col = n0 + wc * 32 + nf * 8 + tg * 2;
            float c0 = acc[mf][nf][0], c1 = acc[mf][nf][1];
            float c2 = acc[mf][nf][2], c3 = acc[mf][nf][3];
            dl0 += c0 * wl[nf][0] + c1 * wl[nf][1];
            dr0 += c0 * wrt[nf][0] + c1 * wrt[nf][1];
            dl1 += c2 * wl[nf][0] + c3 * wl[nf][1];
            dr1 += c2 * wrt[nf][0] + c3 * wrt[nf][1];
            if (r0 < NN) *(float2*)&g_h[((size_t)t * NN + r0) * KD + col] = make_float2(c0, c1);
            if (r1 < NN) *(float2*)&g_h[((size_t)t * NN + r1) * KD + col] = make_float2(c2, c3);
        }
#pragma unroll
        for (int o = 1; o <= 2; o <<= 1) {
            dl0 += __shfl_xor_sync(0xffffffffu, dl0, o);
            dr0 += __shfl_xor_sync(0xffffffffu, dr0, o);
            dl1 += __shfl_xor_sync(0xffffffffu, dl1, o);
            dr1 += __shfl_xor_sync(0xffffffffu, dr1, o);
        }
        if (tg == 0) {
            if (r0 < NN) {
                g_sl[((size_t)t * NN + r0) * HH + head] = dl0;
                g_sr[((size_t)t * NN + r0) * HH + head] = dr0;
            }
            if (r1 < NN) {
                g_sl[((size_t)t * NN + r1) * HH + head] = dl1;
                g_sr[((size_t)t * NN + r1) * HH + head] = dr1;
            }
        }
    }
}

// ---------------- fused gather-aggregate + semantic attention ----------------
__global__ void __launch_bounds__(256) agg_sem_kernel(const float* __restrict__ att_w,
                                                      const float* __restrict__ att_b,
                                                      float* __restrict__ out) {
    int n = (blockIdx.x * blockDim.x + threadIdx.x) >> 5;
    int lane = threadIdx.x & 31;
    if (n >= NN) return;
    int head = lane >> 2;

    float4 o0[TT], o1[TT];

#pragma unroll
    for (int t = 0; t < TT; t++) {
        float srv = g_sr[((size_t)t * NN + n) * HH + head];
        int cnt = g_cnt[t * NN + n];
        cnt = cnt < CAP ? cnt : CAP;
        const int* adj = g_adj + ((size_t)t * NN + n) * CAP;
        float4 a0 = make_float4(0.f, 0.f, 0.f, 0.f);
        float4 a1 = make_float4(0.f, 0.f, 0.f, 0.f);
        float den = 0.f;
        int e = 0;
        for (; e + 4 <= cnt; e += 4) {
            int4 s4 = *(const int4*)(adj + e);
            float sc0 = __ldg(g_sl + ((size_t)t * NN + s4.x) * HH + head) + srv;
            float sc1 = __ldg(g_sl + ((size_t)t * NN + s4.y) * HH + head) + srv;
            float sc2 = __ldg(g_sl + ((size_t)t * NN + s4.z) * HH + head) + srv;
            float sc3 = __ldg(g_sl + ((size_t)t * NN + s4.w) * HH + head) + srv;
            const float4* p0 = (const float4*)(g_h + ((size_t)t * NN + s4.x) * KD + lane * 8);
            const float4* p1 = (const float4*)(g_h + ((size_t)t * NN + s4.y) * KD + lane * 8);
            const float4* p2 = (const float4*)(g_h + ((size_t)t * NN + s4.z) * KD + lane * 8);
            const float4* p3 = (const float4*)(g_h + ((size_t)t * NN + s4.w) * KD + lane * 8);
            float4 u00 = p0[0], u01 = p0[1];
            float4 u10 = p1[0], u11 = p1[1];
            float4 u20 = p2[0], u21 = p2[1];
            float4 u30 = p3[0], u31 = p3[1];
            sc0 = sc0 > 0.f ? sc0 : 0.2f * sc0;
            sc1 = sc1 > 0.f ? sc1 : 0.2f * sc1;
            sc2 = sc2 > 0.f ? sc2 : 0.2f * sc2;
            sc3 = sc3 > 0.f ? sc3 : 0.2f * sc3;
            float x0 = __expf(sc0), x1 = __expf(sc1), x2 = __expf(sc2), x3 = __expf(sc3);
            den += (x0 + x1) + (x2 + x3);
            a0.x += x0 * u00.x + x1 * u10.x + x2 * u20.x + x3 * u30.x;
            a0.y += x0 * u00.y + x1 * u10.y + x2 * u20.y + x3 * u30.y;
            a0.z += x0 * u00.z + x1 * u10.z + x2 * u20.z + x3 * u30.z;
            a0.w += x0 * u00.w + x1 * u10.w + x2 * u20.w + x3 * u30.w;
            a1.x += x0 * u01.x + x1 * u11.x + x2 * u21.x + x3 * u31.x;
            a1.y += x0 * u01.y + x1 * u11.y + x2 * u21.y + x3 * u31.y;
            a1.z += x0 * u01.z + x1 * u11.z + x2 * u21.z + x3 * u31.z;
            a1.w += x0 * u01.w + x1 * u11.w + x2 * u21.w + x3 * u31.w;
        }
        for (; e < cnt; e++) {
            int s0 = __ldg(adj + e);
            float sc0 = __ldg(g_sl + ((size_t)t * NN + s0) * HH + head) + srv;
            const float4* p0 = (const float4*)(g_h + ((size_t)t * NN + s0) * KD + lane * 8);
            float4 u0 = p0[0], u1 = p0[1];
            sc0 = sc0 > 0.f ? sc0 : 0.2f * sc0;
            float x0 = __expf(sc0);
            den += x0;
            a0.x += x0 * u0.x; a0.y += x0 * u0.y; a0.z += x0 * u0.z; a0.w += x0 * u0.w;
            a1.x += x0 * u1.x; a1.y += x0 * u1.y; a1.z += x0 * u1.z; a1.w += x0 * u1.w;
        }
        float inv = den > 0.f ? __frcp_rn(den) : 1.f;
        o0[t] = make_float4(a0.x * inv, a0.y * inv, a0.z * inv, a0.w * inv);
        o1[t] = make_float4(a1.x * inv, a1.y * inv, a1.z * inv, a1.w * inv);
    }

    // semantic attention
    float4 w0 = ((const float4*)att_w)[lane * 2];
    float4 w1 = ((const float4*)att_w)[lane * 2 + 1];
    float b = att_b[0];
    float4 acc0 = make_float4(0.f, 0.f, 0.f, 0.f);
    float4 acc1 = make_float4(0.f, 0.f, 0.f, 0.f);
#pragma unroll
    for (int t = 0; t < TT; t++) {
        float p = o0[t].x * w0.x + o0[t].y * w0.y + o0[t].z * w0.z + o0[t].w * w0.w
                + o1[t].x * w1.x + o1[t].y * w1.y + o1[t].z * w1.z + o1[t].w * w1.w;
#pragma unroll
        for (int o = 16; o; o >>= 1) p += __shfl_xor_sync(0xffffffffu, p, o);
        float att = p + b;
        acc0.x += att * o0[t].x; acc0.y += att * o0[t].y;
        acc0.z += att * o0[t].z; acc0.w += att * o0[t].w;
        acc1.x += att * o1[t].x; acc1.y += att * o1[t].y;
        acc1.z += att * o1[t].z; acc1.w += att * o1[t].w;
    }
    float4* dp = (float4*)(out + (size_t)n * KD + lane * 8);
    dp[0] = acc0;
    dp[1] = acc1;
}

extern "C" void kernel_launch(void* const* d_in, const int* in_sizes, int n_in,
                              void* d_out, int out_size) {
    const float* x     = (const float*)d_in[0];
    const int*   ei    = (const int*)d_in[1];
    const float* W     = (const float*)d_in[2];
    const float* a_l   = (const float*)d_in[3];
    const float* a_r   = (const float*)d_in[4];
    const float* att_w = (const float*)d_in[5];
    const float* att_b = (const float*)d_in[6];
    float* out = (float*)d_out;

    static int smem_set = 0;
    if (!smem_set) {
        cudaFuncSetAttribute(gemm_scores_kernel,
                             cudaFuncAttributeMaxDynamicSharedMemorySize, SM_TOTAL);
        smem_set = 1;
    }

    zero_cnt_kernel<<<(TT * NN + 255) / 256, 256>>>();
    build_kernel<<<(TT * EE + 255) / 256, 256>>>(ei);
    split_W_kernel<<<(TT * KD * KD + 255) / 256, 256>>>(W);

    dim3 ggrid((NN + 127) / 128, 2, TT);
    gemm_scores_kernel<<<ggrid, 256, SM_TOTAL>>>(x, a_l, a_r);

    agg_sem_kernel<<<(NN * 32 + 255) / 256, 256>>>(att_w, att_b, out);
}

// round 8
// speedup vs baseline: 1.5422x; 1.0214x over previous
#include <cuda_runtime.h>
#include <cuda_bf16.h>
#include <cstdint>

#define NN 50000
#define EE 400000
#define TT 3
#define KD 256
#define HH 8
#define HD 32
#define CAP 64   // max in-degree bucket (Poisson(8): max~26, huge margin)

// ---- scratch (device globals; no allocs allowed) ----
__device__ float g_h[TT * NN * KD];      // per-type transformed features
__device__ float g_sl[TT * NN * HH];
__device__ float g_sr[TT * NN * HH];
__device__ int   g_cnt[TT * NN];
__device__ int   g_adj[TT * NN * CAP];
__device__ __nv_bfloat16 g_xh[NN * KD];          // x hi plane
__device__ __nv_bfloat16 g_xl[NN * KD];          // x lo plane
__device__ __nv_bfloat16 g_Wh[TT * KD * KD];     // W^T hi plane  [t][n][k]
__device__ __nv_bfloat16 g_Wl[TT * KD * KD];     // W^T lo plane

static __device__ __forceinline__ uint32_t s2u(const void* p) {
    uint32_t a;
    asm("{ .reg .u64 t; cvta.to.shared.u64 t, %1; cvt.u32.u64 %0, t; }" : "=r"(a) : "l"(p));
    return a;
}
static __device__ __forceinline__ void cp16(uint32_t dst, const void* src, int sz) {
    asm volatile("cp.async.cg.shared.global [%0], [%1], 16, %2;"
                 :: "r"(dst), "l"(src), "r"(sz) : "memory");
}
static __device__ __forceinline__ void mma16(float* c, const uint32_t* a,
                                             uint32_t b0, uint32_t b1) {
    asm volatile(
        "mma.sync.aligned.m16n8k16.row.col.f32.bf16.bf16.f32 "
        "{%0,%1,%2,%3},{%4,%5,%6,%7},{%8,%9},{%0,%1,%2,%3};"
        : "+f"(c[0]), "+f"(c[1]), "+f"(c[2]), "+f"(c[3])
        : "r"(a[0]), "r"(a[1]), "r"(a[2]), "r"(a[3]), "r"(b0), "r"(b1));
}

// ---------------- prep: zero counters ----------------
__global__ void zero_cnt_kernel() {
    int i = blockIdx.x * blockDim.x + threadIdx.x;
    if (i < TT * NN) g_cnt[i] = 0;
}

// ---------------- prep: bucketed CSR build ----------------
__global__ void build_kernel(const int* __restrict__ ei) {
    int i = blockIdx.x * blockDim.x + threadIdx.x;
    if (i >= TT * EE) return;
    int t = i / EE, e = i - t * EE;
    int s = ei[t * 2 * EE + e];
    int d = ei[t * 2 * EE + EE + e];
    int pos = atomicAdd(&g_cnt[t * NN + d], 1);
    if (pos < CAP) g_adj[(t * NN + d) * CAP + pos] = s;
}

// ---------------- prep: split-bf16 planes ----------------
__global__ void split_x_kernel(const float* __restrict__ x) {
    int i = blockIdx.x * blockDim.x + threadIdx.x;
    if (i >= NN * KD) return;
    float v = x[i];
    __nv_bfloat16 h = __float2bfloat16(v);
    g_xh[i] = h;
    g_xl[i] = __float2bfloat16(v - __bfloat162float(h));
}
// W[t][k][n] -> planes [t][n][k]  (reads coalesced: n fastest)
__global__ void split_W_kernel(const float* __restrict__ W) {
    int i = blockIdx.x * blockDim.x + threadIdx.x;
    if (i >= TT * KD * KD) return;
    int n = i & 255, k = (i >> 8) & 255, t = i >> 16;
    float v = W[i];
    __nv_bfloat16 h = __float2bfloat16(v);
    int o = (t << 16) + (n << 8) + k;
    g_Wh[o] = h;
    g_Wl[o] = __float2bfloat16(v - __bfloat162float(h));
}

// ---------------- split-bf16 mma.sync GEMM + fused score epilogue ----------------
// CTA 128x128xK256, BK=16 (one k16 MMA step per kt), 8 warps 2x4, warp tile 64x32.
// SMEM: 4 bf16 planes (Ah,Al,Bh,Bl), each 128 rows x 16 bf16, row stride 12 words
// (bank (12g+tg)%32 all-distinct => conflict-free fragment loads). Double-buffered.
#define ROW_W 12                      // words per row
#define PLANE_W (128 * ROW_W)         // 1536 words per plane
#define BUF_W (4 * PLANE_W)           // 6144 words per buffer
#define SM_TOTAL (2 * BUF_W * 4)      // 49152 B

__global__ void __launch_bounds__(256, 2) gemm_scores_kernel(const float* __restrict__ a_l,
                                                             const float* __restrict__ a_r) {
    extern __shared__ char smraw[];
    uint32_t* smw = (uint32_t*)smraw;
    const uint32_t sbase = s2u(smraw);

    const int tid = threadIdx.x;
    const int wid = tid >> 5, lane = tid & 31;
    const int g = lane >> 2, tg = lane & 3;
    const int wr = wid >> 2, wc = wid & 3;
    const int t = blockIdx.z;
    const int m0 = blockIdx.x * 128, n0 = blockIdx.y * 128;

    float acc[4][4][4];
#pragma unroll
    for (int i = 0; i < 4; i++)
#pragma unroll
        for (int j = 0; j < 4; j++)
#pragma unroll
            for (int q = 0; q < 4; q++) acc[i][j][q] = 0.f;

    const int lr = tid >> 1, half = tid & 1;     // load row / 16B-half
    const int gr = m0 + lr;                       // A global row
    const int nr = n0 + lr;                       // B global row (n index)

    auto loadTile = [&](int kt, int buf) {
        const int k0 = kt * 16;
        uint32_t sb = sbase + (uint32_t)buf * BUF_W * 4;
        uint32_t wo = (uint32_t)(lr * ROW_W + half * 4) * 4;
        int asz = gr < NN ? 16 : 0;
        cp16(sb + wo, g_xh + (size_t)gr * KD + k0 + half * 8, asz);
        cp16(sb + PLANE_W * 4 + wo, g_xl + (size_t)gr * KD + k0 + half * 8, asz);
        size_t woff = ((size_t)t * KD + nr) * KD + k0 + half * 8;
        cp16(sb + 2 * PLANE_W * 4 + wo, g_Wh + woff, 16);
        cp16(sb + 3 * PLANE_W * 4 + wo, g_Wl + woff, 16);
        asm volatile("cp.async.commit_group;" ::: "memory");
    };

    loadTile(0, 0);

    for (int kt = 0; kt < 16; kt++) {
        const int buf = kt & 1;
        if (kt < 15) loadTile(kt + 1, buf ^ 1);
        if (kt < 15) asm volatile("cp.async.wait_group 1;" ::: "memory");
        else         asm volatile("cp.async.wait_group 0;" ::: "memory");
        __syncthreads();

        const uint32_t* Ah = smw + buf * BUF_W;
        const uint32_t* Al = Ah + PLANE_W;
        const uint32_t* Bh = Ah + 2 * PLANE_W;
        const uint32_t* Bl = Ah + 3 * PLANE_W;

        uint32_t ah[4][4], al[4][4];
#pragma unroll
        for (int mf = 0; mf < 4; mf++) {
            int w0 = (wr * 64 + mf * 16 + g) * ROW_W + tg;
            int w1 = w0 + 8 * ROW_W;
            ah[mf][0] = Ah[w0]; ah[mf][1] = Ah[w1];
            ah[mf][2] = Ah[w0 + 4]; ah[mf][3] = Ah[w1 + 4];
            al[mf][0] = Al[w0]; al[mf][1] = Al[w1];
            al[mf][2] = Al[w0 + 4]; al[mf][3] = Al[w1 + 4];
        }
#pragma unroll
        for (int nf = 0; nf < 4; nf++) {
            int nw = (wc * 32 + nf * 8 + g) * ROW_W + tg;
            uint32_t bh0 = Bh[nw], bh1 = Bh[nw + 4];
            uint32_t bl0 = Bl[nw], bl1 = Bl[nw + 4];
#pragma unroll
            for (int mf = 0; mf < 4; mf++) {
                mma16(acc[mf][nf], ah[mf], bh0, bh1);
                mma16(acc[mf][nf], ah[mf], bl0, bl1);
                mma16(acc[mf][nf], al[mf], bh0, bh1);
            }
        }
        __syncthreads();
    }

    // ---- epilogue: store h, compute per-head attention scores ----
    const int head = blockIdx.y * 4 + wc;
    float wl[4][2], wrt[4][2];
#pragma unroll
    for (int nf = 0; nf < 4; nf++) {
        int lc = nf * 8 + tg * 2;
        wl[nf][0]  = __ldg(a_l + ((size_t)t * HH + head) * HD + lc);
        wl[nf][1]  = __ldg(a_l + ((size_t)t * HH + head) * HD + lc + 1);
        wrt[nf][0] = __ldg(a_r + ((size_t)t * HH + head) * HD + lc);
        wrt[nf][1] = __ldg(a_r + ((size_t)t * HH + head) * HD + lc + 1);
    }
#pragma unroll
    for (int mf = 0; mf < 4; mf++) {
        int r0 = m0 + wr * 64 + mf * 16 + g;
        int r1 = r0 + 8;
        float dl0 = 0.f, dr0 = 0.f, dl1 = 0.f, dr1 = 0.f;
#pragma unroll
        for (int nf = 0; nf < 4; nf++) {
            int col = n0 + wc * 32 + nf * 8 + tg * 2;
            float c0 = acc[mf][nf][0], c1 = acc[mf][nf][1];
            float c2 = acc[mf][nf][2], c3 = acc[mf][nf][3];
            dl0 += c0 * wl[nf][0] + c1 * wl[nf][1];
            dr0 += c0 * wrt[nf][0] + c1 * wrt[nf][1];
            dl1 += c2 * wl[nf][0] + c3 * wl[nf][1];
            dr1 += c2 * wrt[nf][0] + c3 * wrt[nf][1];
            if (r0 < NN) *(float2*)&g_h[((size_t)t * NN + r0) * KD + col] = make_float2(c0, c1);
            if (r1 < NN) *(float2*)&g_h[((size_t)t * NN + r1) * KD + col] = make_float2(c2, c3);
        }
#pragma unroll
        for (int o = 1; o <= 2; o <<= 1) {
            dl0 += __shfl_xor_sync(0xffffffffu, dl0, o);
            dr0 += __shfl_xor_sync(0xffffffffu, dr0, o);
            dl1 += __shfl_xor_sync(0xffffffffu, dl1, o);
            dr1 += __shfl_xor_sync(0xffffffffu, dr1, o);
        }
        if (tg == 0) {
            if (r0 < NN) {
                g_sl[((size_t)t * NN + r0) * HH + head] = dl0;
                g_sr[((size_t)t * NN + r0) * HH + head] = dr0;
            }
            if (r1 < NN) {
                g_sl[((size_t)t * NN + r1) * HH + head] = dl1;
                g_sr[((size_t)t * NN + r1) * HH + head] = dr1;
            }
        }
    }
}

// ---------------- fused gather-aggregate + semantic attention ----------------
__global__ void __launch_bounds__(256) agg_sem_kernel(const float* __restrict__ att_w,
                                                      const float* __restrict__ att_b,
                                                      float* __restrict__ out) {
    int n = (blockIdx.x * blockDim.x + threadIdx.x) >> 5;
    int lane = threadIdx.x & 31;
    if (n >= NN) return;
    int head = lane >> 2;

    float4 o0[TT], o1[TT];

#pragma unroll
    for (int t = 0; t < TT; t++) {
        float srv = g_sr[((size_t)t * NN + n) * HH + head];
        int cnt = g_cnt[t * NN + n];
        cnt = cnt < CAP ? cnt : CAP;
        const int* adj = g_adj + ((size_t)t * NN + n) * CAP;
        float4 a0 = make_float4(0.f, 0.f, 0.f, 0.f);
        float4 a1 = make_float4(0.f, 0.f, 0.f, 0.f);
        float den = 0.f;
        int e = 0;
        for (; e + 4 <= cnt; e += 4) {
            int4 s4 = *(const int4*)(adj + e);
            float sc0 = __ldg(g_sl + ((size_t)t * NN + s4.x) * HH + head) + srv;
            float sc1 = __ldg(g_sl + ((size_t)t * NN + s4.y) * HH + head) + srv;
            float sc2 = __ldg(g_sl + ((size_t)t * NN + s4.z) * HH + head) + srv;
            float sc3 = __ldg(g_sl + ((size_t)t * NN + s4.w) * HH + head) + srv;
            const float4* p0 = (const float4*)(g_h + ((size_t)t * NN + s4.x) * KD + lane * 8);
            const float4* p1 = (const float4*)(g_h + ((size_t)t * NN + s4.y) * KD + lane * 8);
            const float4* p2 = (const float4*)(g_h + ((size_t)t * NN + s4.z) * KD + lane * 8);
            const float4* p3 = (const float4*)(g_h + ((size_t)t * NN + s4.w) * KD + lane * 8);
            float4 u00 = p0[0], u01 = p0[1];
            float4 u10 = p1[0], u11 = p1[1];
            float4 u20 = p2[0], u21 = p2[1];
            float4 u30 = p3[0], u31 = p3[1];
            sc0 = sc0 > 0.f ? sc0 : 0.2f * sc0;
            sc1 = sc1 > 0.f ? sc1 : 0.2f * sc1;
            sc2 = sc2 > 0.f ? sc2 : 0.2f * sc2;
            sc3 = sc3 > 0.f ? sc3 : 0.2f * sc3;
            float x0 = __expf(sc0), x1 = __expf(sc1), x2 = __expf(sc2), x3 = __expf(sc3);
            den += (x0 + x1) + (x2 + x3);
            a0.x += x0 * u00.x + x1 * u10.x + x2 * u20.x + x3 * u30.x;
            a0.y += x0 * u00.y + x1 * u10.y + x2 * u20.y + x3 * u30.y;
            a0.z += x0 * u00.z + x1 * u10.z + x2 * u20.z + x3 * u30.z;
            a0.w += x0 * u00.w + x1 * u10.w + x2 * u20.w + x3 * u30.w;
            a1.x += x0 * u01.x + x1 * u11.x + x2 * u21.x + x3 * u31.x;
            a1.y += x0 * u01.y + x1 * u11.y + x2 * u21.y + x3 * u31.y;
            a1.z += x0 * u01.z + x1 * u11.z + x2 * u21.z + x3 * u31.z;
            a1.w += x0 * u01.w + x1 * u11.w + x2 * u21.w + x3 * u31.w;
        }
        for (; e < cnt; e++) {
            int s0 = __ldg(adj + e);
            float sc0 = __ldg(g_sl + ((size_t)t * NN + s0) * HH + head) + srv;
            const float4* p0 = (const float4*)(g_h + ((size_t)t * NN + s0) * KD + lane * 8);
            float4 u0 = p0[0], u1 = p0[1];
            sc0 = sc0 > 0.f ? sc0 : 0.2f * sc0;
            float x0 = __expf(sc0);
            den += x0;
            a0.x += x0 * u0.x; a0.y += x0 * u0.y; a0.z += x0 * u0.z; a0.w += x0 * u0.w;
            a1.x += x0 * u1.x; a1.y += x0 * u1.y; a1.z += x0 * u1.z; a1.w += x0 * u1.w;
        }
        float inv = den > 0.f ? __frcp_rn(den) : 1.f;
        o0[t] = make_float4(a0.x * inv, a0.y * inv, a0.z * inv, a0.w * inv);
        o1[t] = make_float4(a1.x * inv, a1.y * inv, a1.z * inv, a1.w * inv);
    }

    // semantic attention
    float4 w0 = ((const float4*)att_w)[lane * 2];
    float4 w1 = ((const float4*)att_w)[lane * 2 + 1];
    float b = att_b[0];
    float4 acc0 = make_float4(0.f, 0.f, 0.f, 0.f);
    float4 acc1 = make_float4(0.f, 0.f, 0.f, 0.f);
#pragma unroll
    for (int t = 0; t < TT; t++) {
        float p = o0[t].x * w0.x + o0[t].y * w0.y + o0[t].z * w0.z + o0[t].w * w0.w
                + o1[t].x * w1.x + o1[t].y * w1.y + o1[t].z * w1.z + o1[t].w * w1.w;
#pragma unroll
        for (int o = 16; o; o >>= 1) p += __shfl_xor_sync(0xffffffffu, p, o);
        float att = p + b;
        acc0.x += att * o0[t].x; acc0.y += att * o0[t].y;
        acc0.z += att * o0[t].z; acc0.w += att * o0[t].w;
        acc1.x += att * o1[t].x; acc1.y += att * o1[t].y;
        acc1.z += att * o1[t].z; acc1.w += att * o1[t].w;
    }
    float4* dp = (float4*)(out + (size_t)n * KD + lane * 8);
    dp[0] = acc0;
    dp[1] = acc1;
}

extern "C" void kernel_launch(void* const* d_in, const int* in_sizes, int n_in,
                              void* d_out, int out_size) {
    const float* x     = (const float*)d_in[0];
    const int*   ei    = (const int*)d_in[1];
    const float* W     = (const float*)d_in[2];
    const float* a_l   = (const float*)d_in[3];
    const float* a_r   = (const float*)d_in[4];
    const float* att_w = (const float*)d_in[5];
    const float* att_b = (const float*)d_in[6];
    float* out = (float*)d_out;

    static int smem_set = 0;
    if (!smem_set) {
        cudaFuncSetAttribute(gemm_scores_kernel,
                             cudaFuncAttributeMaxDynamicSharedMemorySize, SM_TOTAL);
        smem_set = 1;
    }

    zero_cnt_kernel<<<(TT * NN + 255) / 256, 256>>>();
    build_kernel<<<(TT * EE + 255) / 256, 256>>>(ei);
    split_x_kernel<<<(NN * KD + 255) / 256, 256>>>(x);
    split_W_kernel<<<(TT * KD * KD + 255) / 256, 256>>>(W);

    dim3 ggrid((NN + 127) / 128, 2, TT);
    gemm_scores_kernel<<<ggrid, 256, SM_TOTAL>>>(a_l, a_r);

    agg_sem_kernel<<<(NN * 32 + 255) / 256, 256>>>(att_w, att_b, out);
}